// round 1
// baseline (speedup 1.0000x reference)
#include <cuda_runtime.h>
#include <cstdint>
#include <cub/cub.cuh>

#define NUM_A 9
#define HH 128
#define WW 128
#define NBOX (NUM_A * HH * WW)   /* 147456 */
#define KTOP 6000
#define NPOST 300
#define NMS_NT 1024
#define OWN 6                    /* 1024*6 = 6144 >= 6000 */

__constant__ float c_sizes[NUM_A] = {4.f, 8.f, 12.f, 16.f, 24.f, 32.f, 48.f, 64.f, 96.f};

__device__ unsigned long long g_keys_a[NBOX];
__device__ unsigned long long g_keys_b[NBOX];
__device__ unsigned long long g_k2_a[KTOP];
__device__ unsigned long long g_k2_b[KTOP];
__device__ float4 g_props[KTOP];
__device__ __align__(256) unsigned char g_cub_temp[32u * 1024u * 1024u];

// Decode box exactly like the reference: anchors + deltas, clamp at 0 (all 4
// comps), x2=x1+w BEFORE the min-clips, then [x1, y1, x2-x1, y2-y1].
__device__ __forceinline__ float4 decode_box(int idx, const float4* __restrict__ deltas,
                                             bool* keep)
{
    int a   = idx / (HH * WW);
    int rem = idx - a * (HH * WW);
    int h   = rem >> 7;
    int w   = rem & 127;
    float s    = c_sizes[a];
    float half = s * 0.5f;
    float ax = ((float)h + 0.5f) - half;   // x0 uses the H index (per reference)
    float ay = ((float)w + 0.5f) - half;   // y0 uses the W index
    float4 d = deltas[idx];
    float x1 = fmaxf(ax + d.x, 0.0f);
    float y1 = fmaxf(ay + d.y, 0.0f);
    float bw = fmaxf(s + d.z, 0.0f);
    float bh = fmaxf(s + d.w, 0.0f);
    float x2 = x1 + bw;
    float y2 = y1 + bh;
    x1 = fminf(x1, 128.0f);
    y1 = fminf(y1, 128.0f);
    x2 = fminf(x2, 128.0f);
    y2 = fminf(y2, 128.0f);
    float ow = x2 - x1;
    float oh = y2 - y1;
    *keep = (ow >= 3.0f) && (oh >= 3.0f);
    return make_float4(x1, y1, ow, oh);
}

// Kernel A: per-box sortable key = (flipped score)<<32 | idx.
// Ascending sort then gives (score desc, idx asc) == lax.top_k tie semantics.
__global__ void k_score(const float* __restrict__ scores, const float4* __restrict__ deltas)
{
    int i = blockIdx.x * blockDim.x + threadIdx.x;
    if (i >= NBOX) return;
    bool keep;
    (void)decode_box(i, deltas, &keep);
    float sc = keep ? scores[i] : __int_as_float(0xFF800000);  // -inf
    unsigned u   = __float_as_uint(sc);
    unsigned asc = u ^ ((unsigned)((int)u >> 31) | 0x80000000u); // monotone-increasing map
    unsigned dsc = ~asc;                                         // descending
    g_keys_a[i] = ((unsigned long long)dsc << 32) | (unsigned)i;
}

// Kernel B: rebuild top-6000 props in score-rank order; key2 = (flip y2)<<32 | rank
// -> ascending sort == stable argsort(-y2).
__global__ void k_props(const float4* __restrict__ deltas)
{
    int r = blockIdx.x * blockDim.x + threadIdx.x;
    if (r >= KTOP) return;
    int idx = (int)(unsigned)g_keys_b[r];
    bool keep;
    float4 p = decode_box(idx, deltas, &keep);
    g_props[r] = p;
    float y2 = p.y + p.w;                 // y2 >= 0 -> raw bits are monotone
    unsigned dsc = ~__float_as_uint(y2);
    g_k2_a[r] = ((unsigned long long)dsc << 32) | (unsigned)r;
}

__device__ __forceinline__ unsigned nzmask4(unsigned w)
{
    unsigned r = 0;
    if (w & 0x000000FFu) r |= 1u;
    if (w & 0x0000FF00u) r |= 2u;
    if (w & 0x00FF0000u) r |= 4u;
    if (w & 0xFF000000u) r |= 8u;
    return r;
}

// Kernel C: single-CTA sequential NMS, exact reference semantics:
// for i in 0..K-1: if valid[i]: for all j != i: if iw*ih/area[j] >= 0.7 -> valid[j]=0
// (both directions — later boxes may suppress earlier survivors).
__global__ void __launch_bounds__(NMS_NT, 1) k_nms(float* __restrict__ out)
{
    extern __shared__ char sm_raw[];
    float* sx1 = (float*)sm_raw;
    float* sy1 = sx1 + KTOP;
    float* sx2 = sy1 + KTOP;
    float* sy2 = sx2 + KTOP;
    int*   srd = (int*)(sy2 + KTOP);
    unsigned char* sval = (unsigned char*)(srd + KTOP);  // offset 120000, 16B aligned
    int*   ssc = (int*)(sval + KTOP);                    // 6000 % 16 == 0

    int tid = threadIdx.x;

    // zero output (padded rows must be exactly 0)
    for (int i = tid; i < NPOST * 4; i += NMS_NT) out[i] = 0.0f;

    // gather boxes in y2-sorted order into shared
    for (int m = tid; m < KTOP; m += NMS_NT) {
        int r = (int)(unsigned)g_k2_b[m];
        float4 p = g_props[r];
        float x1 = p.x, y1 = p.y;
        float x2 = x1 + p.z, y2 = y1 + p.w;
        sx1[m] = x1; sy1[m] = y1; sx2[m] = x2; sy2[m] = y2;
        srd[m] = r;
        sval[m] = 1;
    }
    __syncthreads();

    // each thread owns 6 contiguous boxes in registers
    const int base = tid * OWN;
    float rx1[OWN], ry1[OWN], rx2[OWN], ry2[OWN], rar[OWN];
    unsigned rv = 0;
#pragma unroll
    for (int q = 0; q < OWN; ++q) {
        int j = base + q;
        if (j < KTOP) {
            rx1[q] = sx1[j]; ry1[q] = sy1[j];
            rx2[q] = sx2[j]; ry2[q] = sy2[j];
            rar[q] = fmaxf((rx2[q] - rx1[q]) * (ry2[q] - ry1[q]), 1e-6f);
            rv |= 1u << q;
        } else {
            rx1[q] = 0.f; ry1[q] = 0.f; rx2[q] = 0.f; ry2[q] = 0.f; rar[q] = 1.f;
        }
    }

    // sequential scan; skip invalid steps via 16-byte chunked validity mask.
    // Race-safety: no step writes sval at indices in (last_barrier_pos, current_i],
    // so every thread resolves the same next active i.
    int i = 0;
    while (i < KTOP) {
        int cb = i & ~15;
        uint4 v = *(const uint4*)(sval + cb);
        unsigned m16 = nzmask4(v.x) | (nzmask4(v.y) << 4) |
                       (nzmask4(v.z) << 8) | (nzmask4(v.w) << 12);
        m16 >>= (i - cb);
        if (m16 == 0u) { i = cb + 16; continue; }
        i += __ffs(m16) - 1;

        float x1i = sx1[i], y1i = sy1[i], x2i = sx2[i], y2i = sy2[i];
#pragma unroll
        for (int q = 0; q < OWN; ++q) {
            if ((rv >> q) & 1u) {
                int j = base + q;
                if (j != i) {
                    float iw = fminf(x2i, rx2[q]) - fmaxf(x1i, rx1[q]) + 1.0f;
                    float ih = fminf(y2i, ry2[q]) - fmaxf(y1i, ry1[q]) + 1.0f;
                    if (iw > 0.0f && ih > 0.0f) {
                        float ov = __fdiv_rn(iw * ih, rar[q]);  // correctly-rounded, fast-math-proof
                        if (ov >= 0.7f) { rv &= ~(1u << q); sval[j] = 0; }
                    }
                }
            }
        }
        __syncthreads();
        ++i;
    }
    __syncthreads();

    // exclusive prefix over per-thread survivor counts -> output slot (m-order)
    int cnt = __popc(rv);
    ssc[tid] = cnt;
    __syncthreads();
    for (int off = 1; off < NMS_NT; off <<= 1) {
        int add = (tid >= off) ? ssc[tid - off] : 0;
        __syncthreads();
        ssc[tid] += add;
        __syncthreads();
    }
    int pos = ssc[tid] - cnt;
#pragma unroll
    for (int q = 0; q < OWN; ++q) {
        if ((rv >> q) & 1u) {
            if (pos < NPOST) {
                float4 p = g_props[srd[base + q]];
                out[pos * 4 + 0] = p.x;
                out[pos * 4 + 1] = p.y;
                out[pos * 4 + 2] = p.z;
                out[pos * 4 + 3] = p.w;
            }
            ++pos;
        }
    }
}

extern "C" void kernel_launch(void* const* d_in, const int* in_sizes, int n_in,
                              void* d_out, int out_size)
{
    const float*  scores = (const float*)d_in[0];
    const float4* deltas = (const float4*)d_in[1];
    float* out = (float*)d_out;
    (void)in_sizes; (void)n_in; (void)out_size;

    void *p_ka, *p_kb, *p_k2a, *p_k2b, *p_tmp;
    cudaGetSymbolAddress(&p_ka,  g_keys_a);
    cudaGetSymbolAddress(&p_kb,  g_keys_b);
    cudaGetSymbolAddress(&p_k2a, g_k2_a);
    cudaGetSymbolAddress(&p_k2b, g_k2_b);
    cudaGetSymbolAddress(&p_tmp, g_cub_temp);

    k_score<<<(NBOX + 255) / 256, 256>>>(scores, deltas);

    size_t tb = sizeof(g_cub_temp);
    cub::DeviceRadixSort::SortKeys(p_tmp, tb,
        (const unsigned long long*)p_ka, (unsigned long long*)p_kb, NBOX);

    k_props<<<(KTOP + 255) / 256, 256>>>(deltas);

    tb = sizeof(g_cub_temp);
    cub::DeviceRadixSort::SortKeys(p_tmp, tb,
        (const unsigned long long*)p_k2a, (unsigned long long*)p_k2b, KTOP);

    size_t smem = 4u * KTOP * sizeof(float)  // sx1..sy2
                + KTOP * sizeof(int)         // srd
                + KTOP                       // sval
                + NMS_NT * sizeof(int);      // ssc
    cudaFuncSetAttribute(k_nms, cudaFuncAttributeMaxDynamicSharedMemorySize, (int)smem);
    k_nms<<<1, NMS_NT, smem>>>(out);
}

// round 2
// speedup vs baseline: 1.6071x; 1.6071x over previous
#include <cuda_runtime.h>
#include <cstdint>
#include <cub/cub.cuh>

#define NUM_A 9
#define HH 128
#define WW 128
#define NBOX (NUM_A * HH * WW)   /* 147456 */
#define KTOP 6000
#define NPOST 300
#define NMS_NT 1024
#define OWN 6                    /* 1024*6 = 6144 >= 6000 */
#define NWORDS 188               /* ceil(6000/32) */
#define WIN 32

__constant__ float c_sizes[NUM_A] = {4.f, 8.f, 12.f, 16.f, 24.f, 32.f, 48.f, 64.f, 96.f};

__device__ unsigned g_sk_a[NBOX];   // score keys
__device__ unsigned g_sk_b[NBOX];
__device__ unsigned g_sv_a[NBOX];   // values = idx
__device__ unsigned g_sv_b[NBOX];
__device__ unsigned g_yk_a[KTOP];   // y2 keys
__device__ unsigned g_yk_b[KTOP];
__device__ unsigned g_yv_a[KTOP];   // values = rank
__device__ unsigned g_yv_b[KTOP];
__device__ float4 g_props[KTOP];
__device__ __align__(256) unsigned char g_cub_temp[32u * 1024u * 1024u];

// Decode box exactly like the reference.
__device__ __forceinline__ float4 decode_box(int idx, const float4* __restrict__ deltas,
                                             bool* keep)
{
    int a   = idx / (HH * WW);
    int rem = idx - a * (HH * WW);
    int h   = rem >> 7;
    int w   = rem & 127;
    float s    = c_sizes[a];
    float half = s * 0.5f;
    float ax = ((float)h + 0.5f) - half;
    float ay = ((float)w + 0.5f) - half;
    float4 d = deltas[idx];
    float x1 = fmaxf(ax + d.x, 0.0f);
    float y1 = fmaxf(ay + d.y, 0.0f);
    float bw = fmaxf(s + d.z, 0.0f);
    float bh = fmaxf(s + d.w, 0.0f);
    float x2 = x1 + bw;
    float y2 = y1 + bh;
    x1 = fminf(x1, 128.0f);
    y1 = fminf(y1, 128.0f);
    x2 = fminf(x2, 128.0f);
    y2 = fminf(y2, 128.0f);
    float ow = x2 - x1;
    float oh = y2 - y1;
    *keep = (ow >= 3.0f) && (oh >= 3.0f);
    return make_float4(x1, y1, ow, oh);
}

// Kernel A: 32-bit descending score key + idx value. Radix SortPairs is stable,
// so equal keys keep idx-ascending order == lax.top_k tie semantics.
__global__ void k_score(const float* __restrict__ scores, const float4* __restrict__ deltas)
{
    int i = blockIdx.x * blockDim.x + threadIdx.x;
    if (i >= NBOX) return;
    bool keep;
    (void)decode_box(i, deltas, &keep);
    float sc = keep ? scores[i] : __int_as_float(0xFF800000);  // -inf
    unsigned u   = __float_as_uint(sc);
    unsigned asc = u ^ ((unsigned)((int)u >> 31) | 0x80000000u);
    g_sk_a[i] = ~asc;            // descending
    g_sv_a[i] = (unsigned)i;
}

// Kernel B: props for top-6000 in score-rank order; y2 key (descending) + rank value.
__global__ void k_props(const float4* __restrict__ deltas)
{
    int r = blockIdx.x * blockDim.x + threadIdx.x;
    if (r >= KTOP) return;
    int idx = (int)g_sv_b[r];
    bool keep;
    float4 p = decode_box(idx, deltas, &keep);
    g_props[r] = p;
    float y2 = p.y + p.w;              // y2 >= 0 -> raw bits monotone
    g_yk_a[r] = ~__float_as_uint(y2);  // descending
    g_yv_a[r] = (unsigned)r;
}

// Kernel C: windowed exact NMS.
// Control-flow fact: whether step i executes depends only on forward suppression
// from executed k<i. So: gather next 32 valid candidates, warp0 resolves the
// intra-window execution set via the 32x32 forward matrix, then all threads
// apply executed candidates' suppression (both directions) to owned boxes.
__global__ void __launch_bounds__(NMS_NT, 1) k_nms(float* __restrict__ out)
{
    extern __shared__ char sm_raw[];
    float* sx1 = (float*)sm_raw;
    float* sy1 = sx1 + KTOP;
    float* sx2 = sy1 + KTOP;
    float* sy2 = sx2 + KTOP;
    int*   srd = (int*)(sy2 + KTOP);
    unsigned* swords = (unsigned*)(srd + KTOP);      // NWORDS validity bitmask
    int*      scidx  = (int*)(swords + NWORDS);      // WIN candidate m-indices
    float*    scx1   = (float*)(scidx + WIN);
    float*    scy1   = scx1 + WIN;
    float*    scx2   = scy1 + WIN;
    float*    scy2   = scx2 + WIN;
    float*    scar   = scy2 + WIN;
    unsigned* ssupp  = (unsigned*)(scar + WIN);
    int*      sctrl  = (int*)(ssupp + WIN);          // [0]=nc [1]=exec
    int*      ssc    = sctrl + 4;                    // NMS_NT prefix array

    const int tid  = threadIdx.x;
    const int lane = tid & 31;
    const int wid  = tid >> 5;

    for (int i = tid; i < NPOST * 4; i += NMS_NT) out[i] = 0.0f;

    // gather boxes in y2-sorted order
    for (int m = tid; m < KTOP; m += NMS_NT) {
        int r = (int)g_yv_b[m];
        float4 p = g_props[r];
        float x1 = p.x, y1 = p.y;
        sx1[m] = x1; sy1[m] = y1; sx2[m] = x1 + p.z; sy2[m] = y1 + p.w;
        srd[m] = r;
    }
    if (tid < NWORDS) swords[tid] = (tid == NWORDS - 1) ? 0x0000FFFFu : 0xFFFFFFFFu;
    __syncthreads();

    // per-thread owned boxes (registers)
    const int base = tid * OWN;
    float rx1[OWN], ry1[OWN], rx2[OWN], ry2[OWN], rar[OWN];
    unsigned rv = 0;
    float my_ymax2 = -1e30f, my_ymin1 = 1e30f;
#pragma unroll
    for (int q = 0; q < OWN; ++q) {
        int j = base + q;
        if (j < KTOP) {
            rx1[q] = sx1[j]; ry1[q] = sy1[j];
            rx2[q] = sx2[j]; ry2[q] = sy2[j];
            rar[q] = fmaxf((rx2[q] - rx1[q]) * (ry2[q] - ry1[q]), 1e-6f);
            rv |= 1u << q;
            my_ymax2 = fmaxf(my_ymax2, ry2[q]);
            my_ymin1 = fminf(my_ymin1, ry1[q]);
        } else {
            rx1[q] = 0.f; ry1[q] = 0.f; rx2[q] = 0.f; ry2[q] = 0.f; rar[q] = 1.f;
        }
    }

    int p = 0;  // bit cursor (warp 0 register, uniform)

    for (;;) {
        // ---- stage (warp 0): gather next WIN valid candidates, resolve exec ----
        if (wid == 0) {
            int nc = 0;
            while (nc < WIN && p < KTOP) {
                int w0 = p >> 5;
                int widx = w0 + lane;
                unsigned w = (widx < NWORDS) ? swords[widx] : 0u;
                if (lane == 0) w &= (0xFFFFFFFFu << (p & 31));
                int cnt = __popc(w);
                int pre = cnt;
#pragma unroll
                for (int o = 1; o < 32; o <<= 1) {
                    int v = __shfl_up_sync(0xFFFFFFFFu, pre, o);
                    if (lane >= o) pre += v;
                }
                int total = __shfl_sync(0xFFFFFFFFu, pre, 31);
                int r = nc + (pre - cnt);
                unsigned ww = w;
                while (ww && r < WIN) {
                    int b = __ffs(ww) - 1; ww &= ww - 1;
                    scidx[r] = (widx << 5) + b;
                    ++r;
                }
                nc += total; if (nc > WIN) nc = WIN;
                p = (w0 + 32) << 5;
                if (p > KTOP) p = KTOP;
                __syncwarp();
                if (nc == WIN) p = scidx[WIN - 1] + 1;
            }
            // candidate coords + areas
            float mx1 = 0.f, my1 = 0.f, mx2 = 0.f, my2 = 0.f;
            if (lane < nc) {
                int c = scidx[lane];
                mx1 = sx1[c]; my1 = sy1[c]; mx2 = sx2[c]; my2 = sy2[c];
                scx1[lane] = mx1; scy1[lane] = my1;
                scx2[lane] = mx2; scy2[lane] = my2;
                scar[lane] = fmaxf((mx2 - mx1) * (my2 - my1), 1e-6f);
            }
            __syncwarp();
            // forward suppression matrix: supp[l] bit m set if l would suppress m (m>l)
            unsigned supp = 0;
            if (lane < nc) {
                for (int m = lane + 1; m < nc; ++m) {
                    float iw = fminf(mx2, scx2[m]) - fmaxf(mx1, scx1[m]) + 1.0f;
                    float ih = fminf(my2, scy2[m]) - fmaxf(my1, scy1[m]) + 1.0f;
                    if (iw > 0.0f && ih > 0.0f) {
                        float ov = __fdiv_rn(iw * ih, scar[m]);
                        if (ov >= 0.7f) supp |= 1u << m;
                    }
                }
            }
            ssupp[lane] = supp;
            __syncwarp();
            if (lane == 0) {
                unsigned rem = 0, exec = 0;
                for (int l = 0; l < nc; ++l) {
                    if (!((rem >> l) & 1u)) { exec |= 1u << l; rem |= ssupp[l]; }
                }
                sctrl[0] = nc;
                sctrl[1] = (int)exec;
            }
        }
        __syncthreads();   // A: publish candidates + exec

        int ncw = sctrl[0];
        if (ncw == 0) break;
        unsigned exec = (unsigned)sctrl[1];

        // ---- apply: executed candidates suppress owned boxes (both directions) ----
        if (rv) {
            unsigned oldrv = rv;
            unsigned e = exec;
            while (e) {
                int m = __ffs(e) - 1; e &= e - 1;
                float ey1 = scy1[m], ey2 = scy2[m];
                // exact-safe y-interval prune: no own box can have ih > 0
                if (ey2 + 1.0f <= my_ymin1 || ey1 >= my_ymax2 + 1.0f) continue;
                float ex1 = scx1[m], ex2 = scx2[m];
                int ci = scidx[m];
#pragma unroll
                for (int q = 0; q < OWN; ++q) {
                    if ((rv >> q) & 1u) {
                        int j = base + q;
                        if (j != ci) {
                            float iw = fminf(ex2, rx2[q]) - fmaxf(ex1, rx1[q]) + 1.0f;
                            float ih = fminf(ey2, ry2[q]) - fmaxf(ey1, ry1[q]) + 1.0f;
                            if (iw > 0.0f && ih > 0.0f) {
                                float ov = __fdiv_rn(iw * ih, rar[q]);
                                if (ov >= 0.7f) rv &= ~(1u << q);
                            }
                        }
                    }
                }
            }
            unsigned clr = oldrv & ~rv;
            if (clr) {
                unsigned long long m64 = (unsigned long long)clr << (base & 31);
                int w = base >> 5;
                unsigned lo = (unsigned)m64, hi = (unsigned)(m64 >> 32);
                if (lo) atomicAnd(&swords[w], ~lo);
                if (hi) atomicAnd(&swords[w + 1], ~hi);
            }
        }
        __syncthreads();   // B: mask updates visible before next gather
    }

    // ---- output: first NPOST survivors in m-order ----
    __syncthreads();
    int cnt = __popc(rv);
    ssc[tid] = cnt;
    __syncthreads();
    for (int off = 1; off < NMS_NT; off <<= 1) {
        int add = (tid >= off) ? ssc[tid - off] : 0;
        __syncthreads();
        ssc[tid] += add;
        __syncthreads();
    }
    int pos = ssc[tid] - cnt;
#pragma unroll
    for (int q = 0; q < OWN; ++q) {
        if ((rv >> q) & 1u) {
            if (pos < NPOST) {
                float4 pp = g_props[srd[base + q]];
                out[pos * 4 + 0] = pp.x;
                out[pos * 4 + 1] = pp.y;
                out[pos * 4 + 2] = pp.z;
                out[pos * 4 + 3] = pp.w;
            }
            ++pos;
        }
    }
}

extern "C" void kernel_launch(void* const* d_in, const int* in_sizes, int n_in,
                              void* d_out, int out_size)
{
    const float*  scores = (const float*)d_in[0];
    const float4* deltas = (const float4*)d_in[1];
    float* out = (float*)d_out;
    (void)in_sizes; (void)n_in; (void)out_size;

    void *p_ska, *p_skb, *p_sva, *p_svb, *p_yka, *p_ykb, *p_yva, *p_yvb, *p_tmp;
    cudaGetSymbolAddress(&p_ska, g_sk_a);
    cudaGetSymbolAddress(&p_skb, g_sk_b);
    cudaGetSymbolAddress(&p_sva, g_sv_a);
    cudaGetSymbolAddress(&p_svb, g_sv_b);
    cudaGetSymbolAddress(&p_yka, g_yk_a);
    cudaGetSymbolAddress(&p_ykb, g_yk_b);
    cudaGetSymbolAddress(&p_yva, g_yv_a);
    cudaGetSymbolAddress(&p_yvb, g_yv_b);
    cudaGetSymbolAddress(&p_tmp, g_cub_temp);

    k_score<<<(NBOX + 255) / 256, 256>>>(scores, deltas);

    size_t tb = sizeof(g_cub_temp);
    cub::DeviceRadixSort::SortPairs(p_tmp, tb,
        (const unsigned*)p_ska, (unsigned*)p_skb,
        (const unsigned*)p_sva, (unsigned*)p_svb, NBOX);

    k_props<<<(KTOP + 255) / 256, 256>>>(deltas);

    tb = sizeof(g_cub_temp);
    cub::DeviceRadixSort::SortPairs(p_tmp, tb,
        (const unsigned*)p_yka, (unsigned*)p_ykb,
        (const unsigned*)p_yva, (unsigned*)p_yvb, KTOP);

    size_t smem = 4u * KTOP * sizeof(float)        // sx1..sy2
                + KTOP * sizeof(int)               // srd
                + NWORDS * sizeof(unsigned)        // swords
                + WIN * sizeof(int)                // scidx
                + 5u * WIN * sizeof(float)         // scx1..scar
                + WIN * sizeof(unsigned)           // ssupp
                + 4 * sizeof(int)                  // sctrl
                + NMS_NT * sizeof(int);            // ssc
    cudaFuncSetAttribute(k_nms, cudaFuncAttributeMaxDynamicSharedMemorySize, (int)smem);
    k_nms<<<1, NMS_NT, smem>>>(out);
}

// round 3
// speedup vs baseline: 1.6806x; 1.0458x over previous
#include <cuda_runtime.h>
#include <cstdint>
#include <cub/cub.cuh>

#define NUM_A 9
#define HH 128
#define WW 128
#define NBOX (NUM_A * HH * WW)   /* 147456 */
#define KTOP 6000
#define NPOST 300
#define NMS_NT 1024
#define NOWN_T 992               /* warps 0..30 own boxes */
#define OWN 7                    /* 992*7 = 6944 >= 6000 */
#define NWORDS 188               /* ceil(6000/32) */
#define WIN 32
#define STAGE_WARP 31
#define FULLM 0xFFFFFFFFu

__constant__ float c_sizes[NUM_A] = {4.f, 8.f, 12.f, 16.f, 24.f, 32.f, 48.f, 64.f, 96.f};

__device__ unsigned g_sk_a[NBOX];
__device__ unsigned g_sk_b[NBOX];
__device__ unsigned g_sv_a[NBOX];
__device__ unsigned g_sv_b[NBOX];
__device__ unsigned g_yk_a[KTOP];
__device__ unsigned g_yk_b[KTOP];
__device__ unsigned g_yv_a[KTOP];
__device__ unsigned g_yv_b[KTOP];
__device__ float4 g_props[KTOP];
__device__ __align__(256) unsigned char g_cub_temp[32u * 1024u * 1024u];

// ---------------- decode (bit-exact vs reference) ----------------
__device__ __forceinline__ float4 decode_box(int idx, const float4* __restrict__ deltas,
                                             bool* keep)
{
    int a   = idx / (HH * WW);
    int rem = idx - a * (HH * WW);
    int h   = rem >> 7;
    int w   = rem & 127;
    float s    = c_sizes[a];
    float half = s * 0.5f;
    float ax = ((float)h + 0.5f) - half;
    float ay = ((float)w + 0.5f) - half;
    float4 d = deltas[idx];
    float x1 = fmaxf(ax + d.x, 0.0f);
    float y1 = fmaxf(ay + d.y, 0.0f);
    float bw = fmaxf(s + d.z, 0.0f);
    float bh = fmaxf(s + d.w, 0.0f);
    float x2 = x1 + bw;
    float y2 = y1 + bh;
    x1 = fminf(x1, 128.0f);
    y1 = fminf(y1, 128.0f);
    x2 = fminf(x2, 128.0f);
    y2 = fminf(y2, 128.0f);
    float ow = x2 - x1;
    float oh = y2 - y1;
    *keep = (ow >= 3.0f) && (oh >= 3.0f);
    return make_float4(x1, y1, ow, oh);
}

// exact test: rn(n/ar) >= 0.7f, division-free common path.
// 0.7f mantissa is odd -> midpoint rounds to pred -> suppress <=> n > (0.7f - 2^-25)*ar.
__device__ __forceinline__ bool iou_ge(float n, float ar)
{
    float t = fmaf(-0.7f, ar, n);
    if (t >= 0.0f) return true;                 // e >= 0 > -2^-25*ar
    if (t <= -3.2e-8f * ar) return false;       // e <= -2^-25*ar guaranteed
    return __fdiv_rn(n, ar) >= 0.7f;            // rare exact fallback
}

__global__ void k_score(const float* __restrict__ scores, const float4* __restrict__ deltas)
{
    int i = blockIdx.x * blockDim.x + threadIdx.x;
    if (i >= NBOX) return;
    bool keep;
    (void)decode_box(i, deltas, &keep);
    float sc = keep ? scores[i] : __int_as_float(0xFF800000);
    unsigned u   = __float_as_uint(sc);
    unsigned asc = u ^ ((unsigned)((int)u >> 31) | 0x80000000u);
    g_sk_a[i] = ~asc;
    g_sv_a[i] = (unsigned)i;
}

__global__ void k_props(const float4* __restrict__ deltas)
{
    int r = blockIdx.x * blockDim.x + threadIdx.x;
    if (r >= KTOP) return;
    int idx = (int)g_sv_b[r];
    bool keep;
    float4 p = decode_box(idx, deltas, &keep);
    g_props[r] = p;
    float y2 = p.y + p.w;
    g_yk_a[r] = ~__float_as_uint(y2);
    g_yv_a[r] = (unsigned)r;
}

// ---------------- NMS ----------------
struct SmemNMS {
    float sx1[KTOP], sy1[KTOP], sx2[KTOP], sy2[KTOP];
    unsigned swords[NWORDS];
    int   T[132];                 // T[k] = first m with sy2[m] <= (float)k
    int   nc[2];
    int   scidx[2][WIN];
    float cx1[2][WIN], cy1[2][WIN], cx2[2][WIN], cy2[2][WIN];
    int   J1[2][WIN];
    unsigned row[2][WIN];
    int   ssc[NMS_NT];
};

__global__ void __launch_bounds__(NMS_NT, 1) k_nms(float* __restrict__ out)
{
    extern __shared__ char sm_raw[];
    SmemNMS* s = (SmemNMS*)sm_raw;

    const int tid  = threadIdx.x;
    const int lane = tid & 31;
    const int wid  = tid >> 5;

    for (int i = tid; i < NPOST * 4; i += NMS_NT) out[i] = 0.0f;

    // boxes in y2-sorted order
    for (int m = tid; m < KTOP; m += NMS_NT) {
        int r = (int)g_yv_b[m];
        float4 p = g_props[r];
        float x1 = p.x, y1 = p.y;
        s->sx1[m] = x1; s->sy1[m] = y1;
        s->sx2[m] = x1 + p.z; s->sy2[m] = y1 + p.w;
    }
    if (tid < NWORDS) s->swords[tid] = (tid == NWORDS - 1) ? 0x0000FFFFu : 0xFFFFFFFFu;
    __syncthreads();

    // T table: first index with sy2[idx] <= k  (sy2 desc, values in [0,129])
    if (tid < 132) {
        float v = (float)tid;
        int lo = 0, hi = KTOP;
        while (lo < hi) { int mid = (lo + hi) >> 1; if (s->sy2[mid] > v) lo = mid + 1; else hi = mid; }
        s->T[tid] = lo;
    }

    // owned boxes in registers
    const int base = (tid < NOWN_T) ? tid * OWN : KTOP;
    float rx1[OWN], ry1[OWN], rx2[OWN], ry2[OWN], rar[OWN];
    unsigned rv = 0;
    float my_ymin1 = 1e30f;
#pragma unroll
    for (int q = 0; q < OWN; ++q) {
        int j = base + q;
        if (j < KTOP) {
            rx1[q] = s->sx1[j]; ry1[q] = s->sy1[j];
            rx2[q] = s->sx2[j]; ry2[q] = s->sy2[j];
            rar[q] = fmaxf((rx2[q] - rx1[q]) * (ry2[q] - ry1[q]), 1e-6f);
            rv |= 1u << q;
            my_ymin1 = fminf(my_ymin1, ry1[q]);
        } else {
            rx1[q] = 0.f; ry1[q] = 0.f; rx2[q] = 0.f; ry2[q] = 0.f; rar[q] = 1.f;
        }
    }
    __syncthreads();

    int p = 0;  // gather cursor (stage warp only)

    // ---- stage(buf): warp STAGE_WARP only; read-only on swords ----
    auto stage = [&](int buf) {
        int nc = 0;
        while (nc < WIN && p < KTOP) {
            int w0 = p >> 5;
            int widx = w0 + lane;
            unsigned w = (widx < NWORDS) ? s->swords[widx] : 0u;
            if (lane == 0) w &= (0xFFFFFFFFu << (p & 31));
            int cnt = __popc(w);
            int pre = cnt;
#pragma unroll
            for (int o = 1; o < 32; o <<= 1) {
                int v = __shfl_up_sync(FULLM, pre, o);
                if (lane >= o) pre += v;
            }
            int total = __shfl_sync(FULLM, pre, 31);
            int r = nc + (pre - cnt);
            unsigned ww = w;
            while (ww && r < WIN) {
                int b = __ffs(ww) - 1; ww &= ww - 1;
                s->scidx[buf][r] = (widx << 5) + b;
                ++r;
            }
            nc += total; if (nc > WIN) nc = WIN;
            p = (w0 + 32) << 5;
            if (p > KTOP) p = KTOP;
            __syncwarp();
            if (nc == WIN) p = s->scidx[buf][WIN - 1] + 1;
        }
        if (lane < nc) {
            int c = s->scidx[buf][lane];
            float x1 = s->sx1[c], y1 = s->sy1[c], x2 = s->sx2[c], y2 = s->sy2[c];
            s->cx1[buf][lane] = x1; s->cy1[buf][lane] = y1;
            s->cx2[buf][lane] = x2; s->cy2[buf][lane] = y2;
            float thr = y1 - 1.001f;
            int j1;
            if (thr < 0.0f) j1 = KTOP;
            else {
                int kk = (int)thr; if (kk > 131) kk = 131;
                j1 = s->T[kk];          // conservative: T[floor(thr)] >= exact J1
            }
            s->J1[buf][lane] = j1;
        }
        if (lane == 0) s->nc[buf] = nc;
    };

    // ---- matrix(buf): all warps, warp wid computes row wid ----
    auto matrix = [&](int buf) {
        int nc = s->nc[buf];
        if (wid < nc) {
            int m = lane;
            int okp = 0;
            if (m > wid && m < nc) {
                float ax1 = s->cx1[buf][wid], ay1 = s->cy1[buf][wid];
                float ax2 = s->cx2[buf][wid], ay2 = s->cy2[buf][wid];
                float bx1 = s->cx1[buf][m], by1 = s->cy1[buf][m];
                float bx2 = s->cx2[buf][m], by2 = s->cy2[buf][m];
                float arB = fmaxf((bx2 - bx1) * (by2 - by1), 1e-6f);
                float iw = fminf(ax2, bx2) - fmaxf(ax1, bx1) + 1.0f;
                float ih = fminf(ay2, by2) - fmaxf(ay1, by1) + 1.0f;
                if (iw > 0.0f && ih > 0.0f && iou_ge(iw * ih, arB)) okp = 1;
            }
            unsigned rm = __ballot_sync(FULLM, okp);
            if (lane == 0) s->row[buf][wid] = rm;
        }
    };

    // prologue: stage window 0, build its matrix
    if (wid == STAGE_WARP) stage(0);
    __syncthreads();
    matrix(0);
    __syncthreads();

    int cur = 0;
    for (;;) {
        int nc = s->nc[cur];
        if (nc == 0) break;
        int nxt = cur ^ 1;

        unsigned exec = 0;
        // ---- Phase 1 (read-only on swords) ----
        if (wid == STAGE_WARP) {
            stage(nxt);
        } else if (__ballot_sync(FULLM, rv != 0) != 0) {
            int ok = 0;
            if (lane < nc) {
                int c = s->scidx[cur][lane];
                ok = (int)((s->swords[c >> 5] >> (c & 31)) & 1u);
            }
            unsigned validmask = __ballot_sync(FULLM, ok);
            unsigned row = (lane < nc) ? s->row[cur][lane] : 0u;
            unsigned rem = 0;
            for (int l = 0; l < nc; ++l) {
                unsigned rl = __shfl_sync(FULLM, row, l);
                unsigned b = 1u << l;
                if ((validmask & b) && !(rem & b)) { exec |= b; rem |= rl; }
            }
        }
        __syncthreads();

        // ---- Phase 2: matrix for next window + apply current ----
        matrix(nxt);

        if (exec && rv) {
            unsigned oldrv = rv;
            unsigned e = exec;
            while (e) {
                int m = __ffs(e) - 1; e &= e - 1;
                int J1m = s->J1[cur][m];
                if (base >= J1m) continue;
                float ey2 = s->cy2[cur][m];
                if (ey2 + 1.0001f <= my_ymin1) continue;
                float ey1 = s->cy1[cur][m];
                float ex1 = s->cx1[cur][m];
                float ex2 = s->cx2[cur][m];
                int ci = s->scidx[cur][m];
                int qlim = J1m - base; if (qlim > OWN) qlim = OWN;
#pragma unroll
                for (int q = 0; q < OWN; ++q) {
                    if (q < qlim && ((rv >> q) & 1u)) {
                        int j = base + q;
                        if (j != ci) {
                            float iw = fminf(ex2, rx2[q]) - fmaxf(ex1, rx1[q]) + 1.0f;
                            float ih = fminf(ey2, ry2[q]) - fmaxf(ey1, ry1[q]) + 1.0f;
                            if (iw > 0.0f && ih > 0.0f && iou_ge(iw * ih, rar[q]))
                                rv &= ~(1u << q);
                        }
                    }
                }
            }
            unsigned clr = oldrv & ~rv;
            if (clr) {
                unsigned long long m64 = (unsigned long long)clr << (base & 31);
                int w = base >> 5;
                unsigned lo = (unsigned)m64, hi = (unsigned)(m64 >> 32);
                if (lo) atomicAnd(&s->swords[w], ~lo);
                if (hi) atomicAnd(&s->swords[w + 1], ~hi);
            }
        }
        __syncthreads();
        cur = nxt;
    }

    // ---- output: first NPOST survivors in m-order ----
    int cnt = __popc(rv);
    s->ssc[tid] = cnt;
    __syncthreads();
    for (int off = 1; off < NMS_NT; off <<= 1) {
        int add = (tid >= off) ? s->ssc[tid - off] : 0;
        __syncthreads();
        s->ssc[tid] += add;
        __syncthreads();
    }
    int pos = s->ssc[tid] - cnt;
#pragma unroll
    for (int q = 0; q < OWN; ++q) {
        if ((rv >> q) & 1u) {
            if (pos < NPOST) {
                int m = base + q;
                float4 pp = g_props[(int)g_yv_b[m]];
                out[pos * 4 + 0] = pp.x;
                out[pos * 4 + 1] = pp.y;
                out[pos * 4 + 2] = pp.z;
                out[pos * 4 + 3] = pp.w;
            }
            ++pos;
        }
    }
}

extern "C" void kernel_launch(void* const* d_in, const int* in_sizes, int n_in,
                              void* d_out, int out_size)
{
    const float*  scores = (const float*)d_in[0];
    const float4* deltas = (const float4*)d_in[1];
    float* out = (float*)d_out;
    (void)in_sizes; (void)n_in; (void)out_size;

    void *p_ska, *p_skb, *p_sva, *p_svb, *p_yka, *p_ykb, *p_yva, *p_yvb, *p_tmp;
    cudaGetSymbolAddress(&p_ska, g_sk_a);
    cudaGetSymbolAddress(&p_skb, g_sk_b);
    cudaGetSymbolAddress(&p_sva, g_sv_a);
    cudaGetSymbolAddress(&p_svb, g_sv_b);
    cudaGetSymbolAddress(&p_yka, g_yk_a);
    cudaGetSymbolAddress(&p_ykb, g_yk_b);
    cudaGetSymbolAddress(&p_yva, g_yv_a);
    cudaGetSymbolAddress(&p_yvb, g_yv_b);
    cudaGetSymbolAddress(&p_tmp, g_cub_temp);

    k_score<<<(NBOX + 255) / 256, 256>>>(scores, deltas);

    size_t tb = sizeof(g_cub_temp);
    cub::DeviceRadixSort::SortPairs(p_tmp, tb,
        (const unsigned*)p_ska, (unsigned*)p_skb,
        (const unsigned*)p_sva, (unsigned*)p_svb, NBOX);

    k_props<<<(KTOP + 255) / 256, 256>>>(deltas);

    tb = sizeof(g_cub_temp);
    cub::DeviceRadixSort::SortPairs(p_tmp, tb,
        (const unsigned*)p_yka, (unsigned*)p_ykb,
        (const unsigned*)p_yva, (unsigned*)p_yvb, KTOP);

    size_t smem = sizeof(SmemNMS);
    cudaFuncSetAttribute(k_nms, cudaFuncAttributeMaxDynamicSharedMemorySize, (int)smem);
    k_nms<<<1, NMS_NT, smem>>>(out);
}